// round 15
// baseline (speedup 1.0000x reference)
#include <cuda_runtime.h>
#include <cuda_bf16.h>
#include <cuda_fp16.h>

// ---------------------------------------------------------------------------
// OACNNs block, round 15.
//  - conv: smem idx-cache dropped (per-tap __ldg one tap ahead) -> 55.3KB
//    smem -> 4 CTAs/SM (was 3).
//  - submean_exp epilogue: lane-paired red.add.v4 (half the atomic instrs).
//  - mean+cnt share one arena (one memset).
//  - all else identical to round 14 (2482us, rel_err 5.23e-4).
// ---------------------------------------------------------------------------

#define NPTS_MAX 500000
#define SEGTOT   167936     // 4096 + 32768 + 131072
#define TM   128
#define NTHR 256
#define AS   36             // uints per smem row (144B stride, LDSM conflict-free)
#define CBUF   6912        // uints per fp16 buffer (A 4608 + B 2304)
#define COFF_B 4608
#define ROWH   ((size_t)NPTS_MAX * 32)   // uints per fp16 N x 64 buffer
#define CONV_TX 25600u     // 128 rows * 128B + 9216B B tile

// scratch (device globals: allocation-free rule)
__device__ unsigned       g_bufsH[7 * ROWH];     // fp16 P0,P1,P2,Q0,Q1,Q2,Q3 (+reuse)
__device__ unsigned       g_fph[NPTS_MAX * 32];  // fp16 plane of conv input
__device__ float          g_segMeanCnt[SEGTOT * 64 + SEGTOT];  // mean arena + cnt
__device__ float          g_segDen [SEGTOT * 64];
__device__ float          g_segS   [SEGTOT * 64];
__device__ float          g_adpv[NPTS_MAX * 3];
__device__ float          g_statsA[10 * 128];    // 0-6 gemm7, 7 fuse, 8 c1, 9 c2
__device__ unsigned       g_wpack[12 * 2304];    // fp16 tiles (lw,w,proj,fuse)
__device__ unsigned       g_wpackc[54 * 2304];   // fp16 conv tiles

__device__ __constant__ int c_soff[3] = {0, 4096, 36864};

// ---------------- helpers ----------------
__device__ __forceinline__ void red_add_v4(float* addr, float4 v) {
    asm volatile("red.global.add.v4.f32 [%0], {%1,%2,%3,%4};"
                 :: "l"(addr), "f"(v.x), "f"(v.y), "f"(v.z), "f"(v.w)
                 : "memory");
}
__device__ __forceinline__ void cp16(unsigned* dst, const void* src, bool v) {
    unsigned d = (unsigned)__cvta_generic_to_shared(dst);
    int sz = v ? 16 : 0;
    asm volatile("cp.async.cg.shared.global [%0], [%1], 16, %2;"
                 :: "r"(d), "l"(src), "r"(sz) : "memory");
}
__device__ __forceinline__ void cp_commit() {
    asm volatile("cp.async.commit_group;" ::: "memory");
}
template <int N> __device__ __forceinline__ void cp_wait() {
    asm volatile("cp.async.wait_group %0;" :: "n"(N) : "memory");
}
__device__ __forceinline__ void cpbulk(unsigned dst, const void* src,
                                       unsigned bytes, unsigned mba) {
    asm volatile(
        "cp.async.bulk.shared::cluster.global.mbarrier::complete_tx::bytes "
        "[%0], [%1], %2, [%3];"
        :: "r"(dst), "l"(src), "r"(bytes), "r"(mba) : "memory");
}
__device__ __forceinline__ void mbar_init(unsigned mba, unsigned cnt) {
    asm volatile("mbarrier.init.shared.b64 [%0], %1;" :: "r"(mba), "r"(cnt) : "memory");
}
__device__ __forceinline__ void mbar_expect(unsigned mba, unsigned bytes) {
    asm volatile("mbarrier.arrive.expect_tx.shared.b64 _, [%0], %1;"
                 :: "r"(mba), "r"(bytes) : "memory");
}
__device__ __forceinline__ void mbar_wait(unsigned mba, int phase) {
    asm volatile(
        "{\n\t"
        ".reg .pred P;\n\t"
        "LAB_%=:\n\t"
        "mbarrier.try_wait.parity.acquire.cta.shared::cta.b64 P, [%0], %1;\n\t"
        "@!P bra LAB_%=;\n\t"
        "}"
        :: "r"(mba), "r"(phase) : "memory");
}

__device__ __forceinline__ unsigned packh2(float x, float y) {
    __half2 h; h.x = __float2half(x); h.y = __float2half(y);
    return *reinterpret_cast<unsigned*>(&h);
}
__device__ __forceinline__ float4 ldh4(const unsigned* p) {
    uint2 u = *reinterpret_cast<const uint2*>(p);
    __half2 h0 = *reinterpret_cast<__half2*>(&u.x);
    __half2 h1 = *reinterpret_cast<__half2*>(&u.y);
    float2 f0 = __half22float2(h0), f1 = __half22float2(h1);
    return make_float4(f0.x, f0.y, f1.x, f1.y);
}

__device__ __forceinline__ void mma16816h(float* d, unsigned a0, unsigned a1,
                                          unsigned a2, unsigned a3,
                                          unsigned b0, unsigned b1) {
    asm volatile(
        "mma.sync.aligned.m16n8k16.row.col.f32.f16.f16.f32 "
        "{%0,%1,%2,%3}, {%4,%5,%6,%7}, {%8,%9}, {%0,%1,%2,%3};"
        : "+f"(d[0]), "+f"(d[1]), "+f"(d[2]), "+f"(d[3])
        : "r"(a0), "r"(a1), "r"(a2), "r"(a3), "r"(b0), "r"(b1));
}
__device__ __forceinline__ void ldsm4(unsigned& r0, unsigned& r1, unsigned& r2,
                                      unsigned& r3, const unsigned* p) {
    unsigned a = (unsigned)__cvta_generic_to_shared(p);
    asm volatile("ldmatrix.sync.aligned.m8n8.x4.shared.b16 {%0,%1,%2,%3}, [%4];"
                 : "=r"(r0), "=r"(r1), "=r"(r2), "=r"(r3) : "r"(a));
}

__device__ __forceinline__ void a_storeh(unsigned* buf, int r, int c4, float4 v) {
    *reinterpret_cast<uint2*>(buf + r * AS + c4 * 2) =
        make_uint2(packh2(v.x, v.y), packh2(v.z, v.w));
}

__device__ __forceinline__ void stage_Bc(unsigned* Bdst, const unsigned* tile, int tid) {
    const uint4* s = reinterpret_cast<const uint4*>(tile);
    for (int i = tid; i < 576; i += NTHR) cp16(Bdst + i * 4, s + i, true);
}

// 128x64x64 fp16 single-plane mma sweep
__device__ __forceinline__ void mma_compute_h(const unsigned* buf, float acc[8][4],
                                              int wid, int lane) {
    const unsigned* Ap = buf;
    const unsigned* Bp = buf + COFF_B;
    const unsigned* aph = Ap + (wid * 16 + (lane & 15)) * AS + (lane >> 4) * 4;
    int brow = lane & 7;
    int koff = ((lane >> 3) & 1) * 4;
    int ntoff = ((lane >> 4) & 1) * 8 * AS;
#pragma unroll
    for (int kk = 0; kk < 4; ++kk) {
        int ko = kk * 8;
        unsigned a0, a1, a2, a3;
        ldsm4(a0, a1, a2, a3, aph + ko);
#pragma unroll
        for (int np = 0; np < 4; ++np) {
            unsigned b0, b1, b2, b3;
            ldsm4(b0, b1, b2, b3, Bp + (np * 16 + brow) * AS + ntoff + ko + koff);
            mma16816h(acc[2 * np], a0, a1, a2, a3, b0, b1);
            mma16816h(acc[2 * np + 1], a0, a1, a2, a3, b2, b3);
        }
    }
}

// fp16 store + shuffle-reduced fp32 stats; rows >= n masked out of stats
__device__ __forceinline__ void epilogue_stats_h(float acc[8][4], unsigned* __restrict__ Co,
                                                 float* __restrict__ statsg,
                                                 float* csum, float* csq,
                                                 int row0, int n, int wid, int lane, int tid) {
    int g = lane >> 2, c = lane & 3;
    int r0 = row0 + wid * 16 + g, r1 = r0 + 8;
    bool v0 = r0 < n, v1 = r1 < n;
#pragma unroll
    for (int nt = 0; nt < 8; ++nt) {
        int ch = nt * 8 + 2 * c;
        float a0 = v0 ? acc[nt][0] : 0.f;
        float a1 = v0 ? acc[nt][1] : 0.f;
        float a2 = v1 ? acc[nt][2] : 0.f;
        float a3 = v1 ? acc[nt][3] : 0.f;
        if (v0) Co[(size_t)r0 * 32 + (ch >> 1)] = packh2(a0, a1);
        if (v1) Co[(size_t)r1 * 32 + (ch >> 1)] = packh2(a2, a3);
        float s0 = a0 + a2;
        float s1 = a1 + a3;
        float q0 = a0 * a0 + a2 * a2;
        float q1 = a1 * a1 + a3 * a3;
#pragma unroll
        for (int d = 4; d < 32; d <<= 1) {
            s0 += __shfl_xor_sync(0xffffffffu, s0, d);
            s1 += __shfl_xor_sync(0xffffffffu, s1, d);
            q0 += __shfl_xor_sync(0xffffffffu, q0, d);
            q1 += __shfl_xor_sync(0xffffffffu, q1, d);
        }
        if (lane < 4) {
            atomicAdd(&csum[ch], s0);
            atomicAdd(&csum[ch + 1], s1);
            atomicAdd(&csq[ch], q0);
            atomicAdd(&csq[ch + 1], q1);
        }
    }
    __syncthreads();
    if (tid < 64)       atomicAdd(&statsg[tid], csum[tid]);
    else if (tid < 128) atomicAdd(&statsg[tid], csq[tid - 64]);
}

__device__ __forceinline__ void load_coef(float* sc, const float* __restrict__ stats,
                                          const float* __restrict__ g,
                                          const float* __restrict__ b, int n, int tid) {
    if (tid < 64) {
        float inv_n = 1.f / (float)n;
        float mean = stats[tid] * inv_n;
        float var = stats[64 + tid] * inv_n - mean * mean;
        float a = g[tid] * rsqrtf(var + 1e-3f);
        sc[tid] = a;
        sc[64 + tid] = b[tid] - mean * a;
    }
}

// ---------------- prepack (all 66 fp16 n-major tiles, one kernel) ----------------
__global__ void k_prepack_all(const float* __restrict__ Wlw, const float* __restrict__ Ww,
                              const float* __restrict__ Wproj, const float* __restrict__ Wfuse,
                              const float* __restrict__ Wc1, const float* __restrict__ Wc2,
                              unsigned* __restrict__ pack, unsigned* __restrict__ packc) {
    int t = blockIdx.x;     // 0..65
    const float* src;
    unsigned* ph;
    if (t < 3)       { src = Wlw  + t * 4096;        ph = pack  + (size_t)t * 2304; }
    else if (t < 6)  { src = Ww   + (t - 3) * 4096;  ph = pack  + (size_t)t * 2304; }
    else if (t < 10) { src = Wproj+ (t - 6) * 4096;  ph = pack  + (size_t)t * 2304; }
    else if (t < 12) { src = Wfuse+ (t - 10) * 4096; ph = pack  + (size_t)t * 2304; }
    else if (t < 39) { src = Wc1  + (t - 12) * 4096; ph = packc + (size_t)(t - 12) * 2304; }
    else             { src = Wc2  + (t - 39) * 4096; ph = packc + (size_t)(t - 12) * 2304; }
    for (int idx = threadIdx.x; idx < 2048; idx += 256) {
        int cout = idx & 63, p = idx >> 6;
        ph[cout * AS + p] = packh2(src[2 * p * 64 + cout], src[(2 * p + 1) * 64 + cout]);
    }
}

// Hp = fp16(relu(bn(rawF_h)) + feat)
__global__ void k_bnrelu_add_split(const unsigned* __restrict__ RawH,
                                   const float* __restrict__ stats,
                                   const float* __restrict__ g, const float* __restrict__ b,
                                   const float* __restrict__ feat,
                                   unsigned* __restrict__ Hp, int n, int total4) {
    __shared__ float sc[128];
    load_coef(sc, stats, g, b, n, threadIdx.x);
    __syncthreads();
    int i = blockIdx.x * 256 + threadIdx.x;
    if (i >= total4) return;
    int ch = (i & 15) * 4;
    float4 x = ldh4(RawH + (size_t)i * 2);
    float4 r = ((const float4*)feat)[i];
    x.x = fmaxf(x.x * sc[ch + 0] + sc[64 + ch + 0], 0.f) + r.x;
    x.y = fmaxf(x.y * sc[ch + 1] + sc[64 + ch + 1], 0.f) + r.y;
    x.z = fmaxf(x.z * sc[ch + 2] + sc[64 + ch + 2], 0.f) + r.z;
    x.w = fmaxf(x.w * sc[ch + 3] + sc[64 + ch + 3], 0.f) + r.w;
    ((uint2*)Hp)[i] = make_uint2(packh2(x.x, x.y), packh2(x.z, x.w));
}

// fp16 plane = relu(bn(P_h))
__global__ void k_bnrelu_split(const unsigned* __restrict__ Ph, const float* __restrict__ stats,
                               const float* __restrict__ g, const float* __restrict__ b,
                               unsigned* __restrict__ Hp, int n, int total4) {
    __shared__ float sc[128];
    load_coef(sc, stats, g, b, n, threadIdx.x);
    __syncthreads();
    int i = blockIdx.x * 256 + threadIdx.x;
    if (i >= total4) return;
    int ch = (i & 15) * 4;
    float4 x = ldh4(Ph + (size_t)i * 2);
    x.x = fmaxf(x.x * sc[ch + 0] + sc[64 + ch + 0], 0.f);
    x.y = fmaxf(x.y * sc[ch + 1] + sc[64 + ch + 1], 0.f);
    x.z = fmaxf(x.z * sc[ch + 2] + sc[64 + ch + 2], 0.f);
    x.w = fmaxf(x.w * sc[ch + 3] + sc[64 + ch + 3], 0.f);
    ((uint2*)Hp)[i] = make_uint2(packh2(x.x, x.y), packh2(x.z, x.w));
}

// ---------------- tensor-core kernels ----------------
// 7 GEMMs sharing A=feat (fp16-converted in staging) + fused adp softmax.
__global__ __launch_bounds__(NTHR, 4)
void k_mma_gemm7(const float* __restrict__ feat, const float* __restrict__ Wa,
                 const unsigned* __restrict__ pack, unsigned* __restrict__ bufs,
                 float* __restrict__ adp, float* __restrict__ statsg, int n) {
    extern __shared__ unsigned sm[];     // A:[0,4608) B:[4608,6912)
    __shared__ float csum[64], csq[64];
    __shared__ float wa[192];
    const int tidx[7] = {0, 1, 2, 6, 7, 8, 9};
    int tid = threadIdx.x, wid = tid >> 5, lane = tid & 31;
    int row0 = blockIdx.x * TM;
    if (tid < 192) wa[tid] = Wa[tid];
    stage_Bc(sm + COFF_B, pack + (size_t)tidx[0] * 2304, tid);
    cp_commit();
    __syncthreads();     // wa visible
#pragma unroll
    for (int i = 0; i < 8; ++i) {   // convert feat -> fp16 plane, fused adp
        int idx = tid + i * NTHR;
        int r = idx >> 4, c4 = idx & 15;
        int grow = row0 + r;
        float4 v = make_float4(0.f, 0.f, 0.f, 0.f);
        if (grow < n) v = *(const float4*)(feat + (size_t)grow * 64 + c4 * 4);
        a_storeh(sm, r, c4, v);
        int ch = c4 * 4;
        float s0 = v.x * wa[ch * 3 + 0] + v.y * wa[ch * 3 + 3] +
                   v.z * wa[ch * 3 + 6] + v.w * wa[ch * 3 + 9];
        float s1 = v.x * wa[ch * 3 + 1] + v.y * wa[ch * 3 + 4] +
                   v.z * wa[ch * 3 + 7] + v.w * wa[ch * 3 + 10];
        float s2 = v.x * wa[ch * 3 + 2] + v.y * wa[ch * 3 + 5] +
                   v.z * wa[ch * 3 + 8] + v.w * wa[ch * 3 + 11];
#pragma unroll
        for (int d = 1; d < 16; d <<= 1) {
            s0 += __shfl_xor_sync(0xffffffffu, s0, d);
            s1 += __shfl_xor_sync(0xffffffffu, s1, d);
            s2 += __shfl_xor_sync(0xffffffffu, s2, d);
        }
        if ((lane & 15) == 0 && grow < n) {
            float m = fmaxf(s0, fmaxf(s1, s2));
            float e0 = __expf(s0 - m), e1 = __expf(s1 - m), e2 = __expf(s2 - m);
            float inv = 1.f / (e0 + e1 + e2);
            adp[(size_t)grow * 3 + 0] = e0 * inv;
            adp[(size_t)grow * 3 + 1] = e1 * inv;
            adp[(size_t)grow * 3 + 2] = e2 * inv;
        }
    }
    cp_wait<0>();
    __syncthreads();
    for (int t = 0; t < 7; ++t) {
        if (tid < 64) { csum[tid] = 0.f; csq[tid] = 0.f; }
        __syncthreads();
        float acc[8][4] = {};
        mma_compute_h(sm, acc, wid, lane);
        epilogue_stats_h(acc, bufs + (size_t)t * ROWH, statsg + t * 128,
                         csum, csq, row0, n, wid, lane, tid);
        if (t + 1 < 7) {    // all B reads done (epilogue's internal sync)
            stage_Bc(sm + COFF_B, pack + (size_t)tidx[t + 1] * 2304, tid);
            cp_commit();
            cp_wait<0>();
        }
    }
}

// stage one conv tap via cp.async.bulk (index read from gmem, one tap ahead)
__device__ __forceinline__ void conv_stage(unsigned smb, int buf, int k,
                                           const uint4* __restrict__ AF,
                                           const int* __restrict__ nbr,
                                           int row0, int n,
                                           const unsigned* __restrict__ packc,
                                           unsigned mba, int tid) {
    unsigned bbase = smb + (unsigned)buf * (CBUF * 4);
    if (tid < 128) {
        int gr = row0 + tid;
        int sr = (gr < n) ? __ldg(&nbr[(size_t)gr * 27 + k]) : 0;
        cpbulk(bbase + tid * (AS * 4), AF + (size_t)sr * 8, 128, mba);
    } else if (tid == 128) {
        mbar_expect(mba, CONV_TX);
        cpbulk(bbase + COFF_B * 4, packc + (size_t)k * 2304, 9216, mba);
    }
}

// gather conv (fp16), bulk-copy double-buffer pipeline; fp16 out + stats
__global__ __launch_bounds__(NTHR, 4)
void k_mma_convh(const uint4* __restrict__ AF, const int* __restrict__ nbr,
                 const unsigned* __restrict__ packc,
                 unsigned* __restrict__ Co, float* __restrict__ statsg, int n) {
    extern __shared__ unsigned sm[];          // 2 x CBUF
    __shared__ float csum[64], csq[64];
    __shared__ unsigned long long mbar[2];
    int tid = threadIdx.x, wid = tid >> 5, lane = tid & 31;
    int row0 = blockIdx.x * TM;
    unsigned mb0 = (unsigned)__cvta_generic_to_shared(&mbar[0]);
    unsigned mb1 = (unsigned)__cvta_generic_to_shared(&mbar[1]);
    unsigned smb = (unsigned)__cvta_generic_to_shared(sm);
    if (tid < 64) { csum[tid] = 0.f; csq[tid] = 0.f; }
    if (tid == 0) { mbar_init(mb0, 1); mbar_init(mb1, 1); }
    __syncthreads();
    int ph0 = 0, ph1 = 0;
    conv_stage(smb, 0, 0, AF, nbr, row0, n, packc, mb0, tid);
    float acc[8][4] = {};
    for (int k = 0; k < 27; ++k) {
        if (k + 1 < 27)
            conv_stage(smb, (k + 1) & 1, k + 1, AF, nbr, row0, n, packc,
                       (k & 1) ? mb0 : mb1, tid);
        if (k & 1) { mbar_wait(mb1, ph1); ph1 ^= 1; }
        else       { mbar_wait(mb0, ph0); ph0 ^= 1; }
        mma_compute_h(sm + (k & 1) * CBUF, acc, wid, lane);
        __syncthreads();
    }
    epilogue_stats_h(acc, Co, statsg, csum, csq, row0, n, wid, lane, tid);
}

// per-scale (gridDim.y=3): P = exp((relu(bn(P)) - mean[cl]) @ W_w); den += P
__global__ __launch_bounds__(NTHR)
void k_mma_submean_exp(unsigned* __restrict__ bufs, const float* __restrict__ statsb,
                       const float* __restrict__ glw, const float* __restrict__ blw,
                       const unsigned* __restrict__ pack, const float* __restrict__ mean,
                       const float* __restrict__ cnt,
                       const int* __restrict__ cl0, const int* __restrict__ cl1,
                       const int* __restrict__ cl2, float* __restrict__ den, int n) {
    extern __shared__ unsigned buf[];
    __shared__ float coef[128];
    __shared__ int   cls[TM];
    __shared__ float cinv[TM];
    int s = blockIdx.y;
    const int* cl = (s == 0) ? cl0 : ((s == 1) ? cl1 : cl2);
    int soff = c_soff[s];
    unsigned* P = bufs + (size_t)s * ROWH;
    int tid = threadIdx.x, wid = tid >> 5, lane = tid & 31;
    int row0 = blockIdx.x * TM;
    load_coef(coef, statsb + s * 128, glw + s * 64, blw + s * 64, n, tid);
    if (tid < 128) {
        int r = row0 + tid;
        int c = (r < n) ? cl[r] : 0;
        cls[tid] = c;
        cinv[tid] = 1.f / fmaxf(cnt[soff + c], 1.f);
    }
    stage_Bc(buf + COFF_B, pack + (size_t)(3 + s) * 2304, tid);
    cp_commit();
    __syncthreads();
#pragma unroll
    for (int i = 0; i < 8; ++i) {
        int idx = tid + i * NTHR;
        int r = idx >> 4, c4 = idx & 15;
        int grow = row0 + r;
        float4 vv = make_float4(0.f, 0.f, 0.f, 0.f);
        if (grow < n) {
            vv = ldh4(P + (size_t)grow * 32 + c4 * 2);
            float4 ms = *(const float4*)(mean + (size_t)(soff + cls[r]) * 64 + c4 * 4);
            float ci = cinv[r];
            int ch = c4 * 4;
            vv.x = fmaxf(vv.x * coef[ch + 0] + coef[64 + ch + 0], 0.f) - ms.x * ci;
            vv.y = fmaxf(vv.y * coef[ch + 1] + coef[64 + ch + 1], 0.f) - ms.y * ci;
            vv.z = fmaxf(vv.z * coef[ch + 2] + coef[64 + ch + 2], 0.f) - ms.z * ci;
            vv.w = fmaxf(vv.w * coef[ch + 3] + coef[64 + ch + 3], 0.f) - ms.w * ci;
        }
        a_storeh(buf, r, c4, vv);
    }
    cp_wait<0>();
    __syncthreads();
    float acc[8][4] = {};
    mma_compute_h(buf, acc, wid, lane);
    int g = lane >> 2, c = lane & 3;
    int lr0 = wid * 16 + g, lr1 = lr0 + 8;
    int r0 = row0 + lr0, r1 = row0 + lr1;
    bool v0 = r0 < n, v1 = r1 < n;
    float* d0 = den + (size_t)(soff + cls[lr0]) * 64;
    float* d1 = den + (size_t)(soff + cls[lr1]) * 64;
    bool even = (lane & 1) == 0;
#pragma unroll
    for (int nt = 0; nt < 8; ++nt) {
        int ch = nt * 8 + 2 * c;
        // r0 half
        float e0 = __expf(acc[nt][0]), e1 = __expf(acc[nt][1]);
        if (v0) P[(size_t)r0 * 32 + (ch >> 1)] = packh2(e0, e1);
        float n0 = __shfl_down_sync(0xffffffffu, e0, 1);
        float n1 = __shfl_down_sync(0xffffffffu, e1, 1);
        if (v0 && even) red_add_v4(d0 + ch, make_float4(e0, e1, n0, n1));
        // r1 half
        float e2 = __expf(acc[nt][2]), e3 = __expf(acc[nt][3]);
        if (v1) P[(size_t)r1 * 32 + (ch >> 1)] = packh2(e2, e3);
        float n2 = __shfl_down_sync(0xffffffffu, e2, 1);
        float n3 = __shfl_down_sync(0xffffffffu, e3, 1);
        if (v1 && even) red_add_v4(d1 + ch, make_float4(e2, e3, n2, n3));
    }
}

// fuse GEMM: rawF_h = relu(bn(Q3))@Wf[0:64] + mix@Wf[64:128]; fp16 out + stats
__global__ __launch_bounds__(NTHR)
void k_mma_gemm2(const unsigned* __restrict__ Qh, const float* __restrict__ stats,
                 const float* __restrict__ gg, const float* __restrict__ bb,
                 const unsigned* __restrict__ tiles, const float* __restrict__ segS,
                 const int* __restrict__ cl0, const int* __restrict__ cl1,
                 const int* __restrict__ cl2, const float* __restrict__ adp,
                 unsigned* __restrict__ Co, float* __restrict__ statsg, int n) {
    extern __shared__ unsigned buf[];
    __shared__ float csum[64], csq[64];
    __shared__ float coef[128];
    __shared__ int   cls[3][TM];
    __shared__ float sad[3][TM];
    int tid = threadIdx.x, wid = tid >> 5, lane = tid & 31;
    int row0 = blockIdx.x * TM;
    if (tid < 64) { csum[tid] = 0.f; csq[tid] = 0.f; }
    load_coef(coef, stats, gg, bb, n, tid);
    if (tid < 128) {
        int r = row0 + tid;
        bool v = r < n;
        cls[0][tid] = v ? cl0[r] : 0;
        cls[1][tid] = v ? cl1[r] : 0;
        cls[2][tid] = v ? cl2[r] : 0;
        sad[0][tid] = v ? adp[(size_t)r * 3 + 0] : 0.f;
        sad[1][tid] = v ? adp[(size_t)r * 3 + 1] : 0.f;
        sad[2][tid] = v ? adp[(size_t)r * 3 + 2] : 0.f;
    }
    __syncthreads();
    float acc[8][4] = {};
#pragma unroll
    for (int p = 0; p < 2; ++p) {
        stage_Bc(buf + COFF_B, tiles + (size_t)p * 2304, tid);
        cp_commit();
#pragma unroll
        for (int i = 0; i < 8; ++i) {
            int idx = tid + i * NTHR;
            int r = idx >> 4, c4 = idx & 15;
            int grow = row0 + r;
            float4 vv = make_float4(0.f, 0.f, 0.f, 0.f);
            if (grow < n) {
                if (p == 0) {
                    vv = ldh4(Qh + (size_t)grow * 32 + c4 * 2);
                    int ch = c4 * 4;
                    vv.x = fmaxf(vv.x * coef[ch + 0] + coef[64 + ch + 0], 0.f);
                    vv.y = fmaxf(vv.y * coef[ch + 1] + coef[64 + ch + 1], 0.f);
                    vv.z = fmaxf(vv.z * coef[ch + 2] + coef[64 + ch + 2], 0.f);
                    vv.w = fmaxf(vv.w * coef[ch + 3] + coef[64 + ch + 3], 0.f);
                } else {
                    float w0 = sad[0][r], w1 = sad[1][r], w2 = sad[2][r];
                    float4 a = *(const float4*)(segS + (size_t)(0 + cls[0][r]) * 64 + c4 * 4);
                    float4 bv = *(const float4*)(segS + (size_t)(4096 + cls[1][r]) * 64 + c4 * 4);
                    float4 cc = *(const float4*)(segS + (size_t)(36864 + cls[2][r]) * 64 + c4 * 4);
                    vv.x = w0 * a.x + w1 * bv.x + w2 * cc.x;
                    vv.y = w0 * a.y + w1 * bv.y + w2 * cc.y;
                    vv.z = w0 * a.z + w1 * bv.z + w2 * cc.z;
                    vv.w = w0 * a.w + w1 * bv.w + w2 * cc.w;
                }
            }
            a_storeh(buf, r, c4, vv);
        }
        cp_wait<0>();
        __syncthreads();
        mma_compute_h(buf, acc, wid, lane);
        __syncthreads();
    }
    epilogue_stats_h(acc, Co, statsg, csum, csq, row0, n, wid, lane, tid);
}

// ---------------- small / elementwise kernels ----------------
// per-scale (gridDim.y=3): mean-arena += relu(bn(P_h)), cnt++
__global__ void k_segsum3(const unsigned* __restrict__ bufs, const float* __restrict__ statsb,
                          const float* __restrict__ glw, const float* __restrict__ blw,
                          const int* __restrict__ cl0, const int* __restrict__ cl1,
                          const int* __restrict__ cl2, float* __restrict__ mean,
                          float* __restrict__ cnt, int n) {
    __shared__ float sc[128];
    int s = blockIdx.y;
    load_coef(sc, statsb + s * 128, glw + s * 64, blw + s * 64, n, threadIdx.x);
    __syncthreads();
    int row = blockIdx.x * blockDim.x + threadIdx.x;
    if (row >= n) return;
    const int* cl = (s == 0) ? cl0 : ((s == 1) ? cl1 : cl2);
    int c = c_soff[s] + cl[row];
    const unsigned* p = bufs + (size_t)s * ROWH + (size_t)row * 32;
    float* sg = mean + (size_t)c * 64;
#pragma unroll
    for (int c4 = 0; c4 < 16; ++c4) {
        float4 x = ldh4(p + c4 * 2);
        x.x = fmaxf(x.x * sc[c4 * 4 + 0] + sc[64 + c4 * 4 + 0], 0.f);
        x.y = fmaxf(x.y * sc[c4 * 4 + 1] + sc[64 + c4 * 4 + 1], 0.f);
        x.z = fmaxf(x.z * sc[c4 * 4 + 2] + sc[64 + c4 * 4 + 2], 0.f);
        x.w = fmaxf(x.w * sc[c4 * 4 + 3] + sc[64 + c4 * 4 + 3], 0.f);
        red_add_v4(sg + c4 * 4, x);
    }
    atomicAdd(&cnt[c], 1.f);
}

// per-scale (gridDim.y=3): segS += relu(bn(Q_h)) * expP_h / (den[cl]+1e-6)
__global__ void k_pw3(const unsigned* __restrict__ bufs, const float* __restrict__ statsb,
                      const float* __restrict__ gproj, const float* __restrict__ bproj,
                      const float* __restrict__ den,
                      const int* __restrict__ cl0, const int* __restrict__ cl1,
                      const int* __restrict__ cl2, float* __restrict__ segS, int n) {
    __shared__ float sc[128];
    int s = blockIdx.y;
    load_coef(sc, statsb + (3 + s) * 128, gproj + s * 64, bproj + s * 64, n, threadIdx.x);
    __syncthreads();
    int row = blockIdx.x * blockDim.x + threadIdx.x;
    if (row >= n) return;
    const int* cl = (s == 0) ? cl0 : ((s == 1) ? cl1 : cl2);
    int c = c_soff[s] + cl[row];
    const unsigned* q = bufs + (size_t)(3 + s) * ROWH + (size_t)row * 32;
    const unsigned* p = bufs + (size_t)s * ROWH + (size_t)row * 32;
    const float* d = den + (size_t)c * 64;
    float* sg = segS + (size_t)c * 64;
#pragma unroll
    for (int c4 = 0; c4 < 16; ++c4) {
        float4 qv = ldh4(q + c4 * 2);
        float4 pv = ldh4(p + c4 * 2);
        float4 dv = *(const float4*)(d + c4 * 4);
        float4 o;
        o.x = fmaxf(qv.x * sc[c4 * 4 + 0] + sc[64 + c4 * 4 + 0], 0.f) * pv.x / (dv.x + 1e-6f);
        o.y = fmaxf(qv.y * sc[c4 * 4 + 1] + sc[64 + c4 * 4 + 1], 0.f) * pv.y / (dv.y + 1e-6f);
        o.z = fmaxf(qv.z * sc[c4 * 4 + 2] + sc[64 + c4 * 4 + 2], 0.f) * pv.z / (dv.z + 1e-6f);
        o.w = fmaxf(qv.w * sc[c4 * 4 + 3] + sc[64 + c4 * 4 + 3], 0.f) * pv.w / (dv.w + 1e-6f);
        red_add_v4(sg + c4 * 4, o);
    }
}

// out = relu(bn_c2(H_h) + F), F = relu(bn_fuse(rawF_h)) + feat (recomputed)
__global__ void k_final(const unsigned* __restrict__ Hh, const float* __restrict__ statsC,
                        const float* __restrict__ gC, const float* __restrict__ bC,
                        const unsigned* __restrict__ RawH, const float* __restrict__ statsF,
                        const float* __restrict__ gF, const float* __restrict__ bF,
                        const float* __restrict__ feat, float* __restrict__ out,
                        int n, int total4) {
    __shared__ float sc[128];   // conv2 coef
    __shared__ float sf[128];   // fuse coef
    load_coef(sc, statsC, gC, bC, n, threadIdx.x);
    if (threadIdx.x >= 128) load_coef(sf, statsF, gF, bF, n, threadIdx.x - 128);
    __syncthreads();
    int i = blockIdx.x * 256 + threadIdx.x;
    if (i >= total4) return;
    int ch = (i & 15) * 4;
    float4 h = ldh4(Hh + (size_t)i * 2);
    float4 w = ldh4(RawH + (size_t)i * 2);
    float4 r = ((const float4*)feat)[i];
    float f0 = fmaxf(w.x * sf[ch + 0] + sf[64 + ch + 0], 0.f) + r.x;
    float f1 = fmaxf(w.y * sf[ch + 1] + sf[64 + ch + 1], 0.f) + r.y;
    float f2 = fmaxf(w.z * sf[ch + 2] + sf[64 + ch + 2], 0.f) + r.z;
    float f3 = fmaxf(w.w * sf[ch + 3] + sf[64 + ch + 3], 0.f) + r.w;
    float4 x;
    x.x = fmaxf(h.x * sc[ch + 0] + sc[64 + ch + 0] + f0, 0.f);
    x.y = fmaxf(h.y * sc[ch + 1] + sc[64 + ch + 1] + f1, 0.f);
    x.z = fmaxf(h.z * sc[ch + 2] + sc[64 + ch + 2] + f2, 0.f);
    x.w = fmaxf(h.w * sc[ch + 3] + sc[64 + ch + 3] + f3, 0.f);
    ((float4*)out)[i] = x;
}

// ---------------------------------------------------------------------------
extern "C" void kernel_launch(void* const* d_in, const int* in_sizes, int n_in,
                              void* d_out, int out_size) {
    const float* feat   = (const float*)d_in[0];
    const int*   cl0    = (const int*)d_in[1];
    const int*   cl1    = (const int*)d_in[2];
    const int*   cl2    = (const int*)d_in[3];
    const int*   nbr    = (const int*)d_in[4];
    const float* W_lw   = (const float*)d_in[5];
    const float* g_lw   = (const float*)d_in[6];
    const float* b_lw   = (const float*)d_in[7];
    const float* W_w    = (const float*)d_in[8];
    const float* W_proj = (const float*)d_in[9];
    const float* g_proj = (const float*)d_in[10];
    const float* b_proj = (const float*)d_in[11];
    const float* W_adp  = (const float*)d_in[12];
    const float* W_fuse = (const float*)d_in[13];
    const float* g_fuse = (const float*)d_in[14];
    const float* b_fuse = (const float*)d_in[15];
    const float* W_c1   = (const float*)d_in[16];
    const float* g_c1   = (const float*)d_in[17];
    const float* b_c1   = (const float*)d_in[18];
    const float* W_c2   = (const float*)d_in[19];
    const float* g_c2   = (const float*)d_in[20];
    const float* b_c2   = (const float*)d_in[21];
    float* out = (float*)d_out;
    int n = in_sizes[1];

    float *pMeanCnt, *pDen, *pSegS, *pStats, *pAdp;
    unsigned *pBufH, *pPack, *pPackC, *pFph;
    cudaGetSymbolAddress((void**)&pBufH, g_bufsH);
    cudaGetSymbolAddress((void**)&pFph, g_fph);
    cudaGetSymbolAddress((void**)&pMeanCnt, g_segMeanCnt);
    cudaGetSymbolAddress((void**)&pDen, g_segDen);
    cudaGetSymbolAddress((void**)&pSegS, g_segS);
    cudaGetSymbolAddress((void**)&pStats, g_statsA);
    cudaGetSymbolAddress((void**)&pAdp, g_adpv);
    cudaGetSymbolAddress((void**)&pPack, g_wpack);
    cudaGetSymbolAddress((void**)&pPackC, g_wpackc);
    float* pMean = pMeanCnt;
    float* pCnt  = pMeanCnt + (size_t)SEGTOT * 64;

    const int GB = (n + TM - 1) / TM;
    const int EB = (n + 255) / 256;
    const int total4 = n * 16;
    const int SB = (total4 + 255) / 256;
    const int SM_1  = CBUF * 4;                     // 27648B (fp16 A + B)
    const int SM_CV = 2 * CBUF * 4;                 // 55296B -> 4 CTAs/SM

    cudaFuncSetAttribute(k_mma_gemm7, cudaFuncAttributeMaxDynamicSharedMemorySize, SM_1);
    cudaFuncSetAttribute(k_mma_submean_exp, cudaFuncAttributeMaxDynamicSharedMemorySize, SM_1);
    cudaFuncSetAttribute(k_mma_gemm2, cudaFuncAttributeMaxDynamicSharedMemorySize, SM_1);
    cudaFuncSetAttribute(k_mma_convh, cudaFuncAttributeMaxDynamicSharedMemorySize, SM_CV);

    const uint4* AF = (const uint4*)pFph;
    unsigned* Qh3 = pBufH + 6 * ROWH;
    unsigned* RawFH = pBufH;                // slot 0 (P0, free after pw3)
    unsigned* C1H  = pBufH + 1 * ROWH;      // slot 1
    unsigned* C2H  = pBufH + 2 * ROWH;      // slot 2

    k_prepack_all<<<66, 256>>>(W_lw, W_w, W_proj, W_fuse, W_c1, W_c2, pPack, pPackC);
    cudaMemsetAsync(pStats, 0, 10 * 128 * sizeof(float));

    // 7 feat-GEMMs (feat converted in staging) + fused adp
    k_mma_gemm7<<<GB, NTHR, SM_1>>>(feat, W_adp, pPack, pBufH, pAdp, pStats, n);

    // cluster attention, all 3 scales batched
    cudaMemsetAsync(pMeanCnt, 0, ((size_t)SEGTOT * 64 + SEGTOT) * sizeof(float));
    k_segsum3<<<dim3(EB, 3), 256>>>(pBufH, pStats, g_lw, b_lw, cl0, cl1, cl2,
                                    pMean, pCnt, n);
    cudaMemsetAsync(pDen, 0, (size_t)SEGTOT * 64 * sizeof(float));
    k_mma_submean_exp<<<dim3(GB, 3), NTHR, SM_1>>>(pBufH, pStats, g_lw, b_lw, pPack,
                                                   pMean, pCnt, cl0, cl1, cl2, pDen, n);
    cudaMemsetAsync(pSegS, 0, (size_t)SEGTOT * 64 * sizeof(float));
    k_pw3<<<dim3(EB, 3), 256>>>(pBufH, pStats, g_proj, b_proj, pDen,
                                cl0, cl1, cl2, pSegS, n);

    // fused: rawF_h = [relu(bn(Q3)), mix] @ W_fuse  (F recomputed in k_final)
    k_mma_gemm2<<<GB, NTHR, SM_1>>>(Qh3, pStats + 6 * 128, g_proj + 192, b_proj + 192,
                                    pPack + (size_t)10 * 2304, pSegS,
                                    cl0, cl1, cl2, pAdp, RawFH, pStats + 7 * 128, n);
    k_bnrelu_add_split<<<SB, 256>>>(RawFH, pStats + 7 * 128, g_fuse, b_fuse, feat,
                                    pFph, n, total4);
    // conv1 -> split ; conv2 -> final (recomputes F)
    k_mma_convh<<<GB, NTHR, SM_CV>>>(AF, nbr, pPackC, C1H, pStats + 8 * 128, n);
    k_bnrelu_split<<<SB, 256>>>(C1H, pStats + 8 * 128, g_c1, b_c1, pFph, n, total4);
    k_mma_convh<<<GB, NTHR, SM_CV>>>(AF, nbr, pPackC + (size_t)27 * 2304,
                                     C2H, pStats + 9 * 128, n);
    k_final<<<SB, 256>>>(C2H, pStats + 9 * 128, g_c2, b_c2,
                         RawFH, pStats + 7 * 128, g_fuse, b_fuse,
                         feat, out, n, total4);
}

// round 17
// speedup vs baseline: 1.4426x; 1.4426x over previous
#include <cuda_runtime.h>
#include <cuda_bf16.h>
#include <cuda_fp16.h>

// ---------------------------------------------------------------------------
// OACNNs block, round 16 = round 14 (2482us best) + single-memset seg arenas.
//  - conv: smem idx cache, depth-1 bulk double-buffer (measured optimum).
//  - submean_exp: red.add.v2 epilogue (measured optimum).
//  - seg arenas (mean, den, segS, cnt) contiguous -> one memset.
// ---------------------------------------------------------------------------

#define NPTS_MAX 500000
#define SEGTOT   167936     // 4096 + 32768 + 131072
#define TM   128
#define NTHR 256
#define AS   36             // uints per smem row (144B stride, LDSM conflict-free)
#define CBUF   6912        // uints per fp16 buffer (A 4608 + B 2304)
#define COFF_B 4608
#define ROWH   ((size_t)NPTS_MAX * 32)   // uints per fp16 N x 64 buffer
#define CONV_TX 25600u     // 128 rows * 128B + 9216B B tile
#define SEGSZ  ((size_t)SEGTOT * 64)

// scratch (device globals: allocation-free rule)
__device__ unsigned       g_bufsH[7 * ROWH];     // fp16 P0,P1,P2,Q0,Q1,Q2,Q3 (+reuse)
__device__ unsigned       g_fph[NPTS_MAX * 32];  // fp16 plane of conv input
__device__ float          g_segAll[3 * SEGSZ + SEGTOT];  // mean | den | segS | cnt
__device__ float          g_adpv[NPTS_MAX * 3];
__device__ float          g_statsA[10 * 128];    // 0-6 gemm7, 7 fuse, 8 c1, 9 c2
__device__ unsigned       g_wpack[12 * 2304];    // fp16 tiles (lw,w,proj,fuse)
__device__ unsigned       g_wpackc[54 * 2304];   // fp16 conv tiles

__device__ __constant__ int c_soff[3] = {0, 4096, 36864};

// ---------------- helpers ----------------
__device__ __forceinline__ void red_add_v4(float* addr, float4 v) {
    asm volatile("red.global.add.v4.f32 [%0], {%1,%2,%3,%4};"
                 :: "l"(addr), "f"(v.x), "f"(v.y), "f"(v.z), "f"(v.w)
                 : "memory");
}
__device__ __forceinline__ void red_add_v2(float* addr, float x, float y) {
    asm volatile("red.global.add.v2.f32 [%0], {%1,%2};"
                 :: "l"(addr), "f"(x), "f"(y) : "memory");
}
__device__ __forceinline__ void cp16(unsigned* dst, const void* src, bool v) {
    unsigned d = (unsigned)__cvta_generic_to_shared(dst);
    int sz = v ? 16 : 0;
    asm volatile("cp.async.cg.shared.global [%0], [%1], 16, %2;"
                 :: "r"(d), "l"(src), "r"(sz) : "memory");
}
__device__ __forceinline__ void cp_commit() {
    asm volatile("cp.async.commit_group;" ::: "memory");
}
template <int N> __device__ __forceinline__ void cp_wait() {
    asm volatile("cp.async.wait_group %0;" :: "n"(N) : "memory");
}
__device__ __forceinline__ void cpbulk(unsigned dst, const void* src,
                                       unsigned bytes, unsigned mba) {
    asm volatile(
        "cp.async.bulk.shared::cluster.global.mbarrier::complete_tx::bytes "
        "[%0], [%1], %2, [%3];"
        :: "r"(dst), "l"(src), "r"(bytes), "r"(mba) : "memory");
}
__device__ __forceinline__ void mbar_init(unsigned mba, unsigned cnt) {
    asm volatile("mbarrier.init.shared.b64 [%0], %1;" :: "r"(mba), "r"(cnt) : "memory");
}
__device__ __forceinline__ void mbar_expect(unsigned mba, unsigned bytes) {
    asm volatile("mbarrier.arrive.expect_tx.shared.b64 _, [%0], %1;"
                 :: "r"(mba), "r"(bytes) : "memory");
}
__device__ __forceinline__ void mbar_wait(unsigned mba, int phase) {
    asm volatile(
        "{\n\t"
        ".reg .pred P;\n\t"
        "LAB_%=:\n\t"
        "mbarrier.try_wait.parity.acquire.cta.shared::cta.b64 P, [%0], %1;\n\t"
        "@!P bra LAB_%=;\n\t"
        "}"
        :: "r"(mba), "r"(phase) : "memory");
}

__device__ __forceinline__ unsigned packh2(float x, float y) {
    __half2 h; h.x = __float2half(x); h.y = __float2half(y);
    return *reinterpret_cast<unsigned*>(&h);
}
__device__ __forceinline__ float4 ldh4(const unsigned* p) {
    uint2 u = *reinterpret_cast<const uint2*>(p);
    __half2 h0 = *reinterpret_cast<__half2*>(&u.x);
    __half2 h1 = *reinterpret_cast<__half2*>(&u.y);
    float2 f0 = __half22float2(h0), f1 = __half22float2(h1);
    return make_float4(f0.x, f0.y, f1.x, f1.y);
}

__device__ __forceinline__ void mma16816h(float* d, unsigned a0, unsigned a1,
                                          unsigned a2, unsigned a3,
                                          unsigned b0, unsigned b1) {
    asm volatile(
        "mma.sync.aligned.m16n8k16.row.col.f32.f16.f16.f32 "
        "{%0,%1,%2,%3}, {%4,%5,%6,%7}, {%8,%9}, {%0,%1,%2,%3};"
        : "+f"(d[0]), "+f"(d[1]), "+f"(d[2]), "+f"(d[3])
        : "r"(a0), "r"(a1), "r"(a2), "r"(a3), "r"(b0), "r"(b1));
}
__device__ __forceinline__ void ldsm4(unsigned& r0, unsigned& r1, unsigned& r2,
                                      unsigned& r3, const unsigned* p) {
    unsigned a = (unsigned)__cvta_generic_to_shared(p);
    asm volatile("ldmatrix.sync.aligned.m8n8.x4.shared.b16 {%0,%1,%2,%3}, [%4];"
                 : "=r"(r0), "=r"(r1), "=r"(r2), "=r"(r3) : "r"(a));
}

__device__ __forceinline__ void a_storeh(unsigned* buf, int r, int c4, float4 v) {
    *reinterpret_cast<uint2*>(buf + r * AS + c4 * 2) =
        make_uint2(packh2(v.x, v.y), packh2(v.z, v.w));
}

__device__ __forceinline__ void stage_Bc(unsigned* Bdst, const unsigned* tile, int tid) {
    const uint4* s = reinterpret_cast<const uint4*>(tile);
    for (int i = tid; i < 576; i += NTHR) cp16(Bdst + i * 4, s + i, true);
}

// 128x64x64 fp16 single-plane mma sweep
__device__ __forceinline__ void mma_compute_h(const unsigned* buf, float acc[8][4],
                                              int wid, int lane) {
    const unsigned* Ap = buf;
    const unsigned* Bp = buf + COFF_B;
    const unsigned* aph = Ap + (wid * 16 + (lane & 15)) * AS + (lane >> 4) * 4;
    int brow = lane & 7;
    int koff = ((lane >> 3) & 1) * 4;
    int ntoff = ((lane >> 4) & 1) * 8 * AS;
#pragma unroll
    for (int kk = 0; kk < 4; ++kk) {
        int ko = kk * 8;
        unsigned a0, a1, a2, a3;
        ldsm4(a0, a1, a2, a3, aph + ko);
#pragma unroll
        for (int np = 0; np < 4; ++np) {
            unsigned b0, b1, b2, b3;
            ldsm4(b0, b1, b2, b3, Bp + (np * 16 + brow) * AS + ntoff + ko + koff);
            mma16816h(acc[2 * np], a0, a1, a2, a3, b0, b1);
            mma16816h(acc[2 * np + 1], a0, a1, a2, a3, b2, b3);
        }
    }
}

// fp16 store + shuffle-reduced fp32 stats; rows >= n masked out of stats
__device__ __forceinline__ void epilogue_stats_h(float acc[8][4], unsigned* __restrict__ Co,
                                                 float* __restrict__ statsg,
                                                 float* csum, float* csq,
                                                 int row0, int n, int wid, int lane, int tid) {
    int g = lane >> 2, c = lane & 3;
    int r0 = row0 + wid * 16 + g, r1 = r0 + 8;
    bool v0 = r0 < n, v1 = r1 < n;
#pragma unroll
    for (int nt = 0; nt < 8; ++nt) {
        int ch = nt * 8 + 2 * c;
        float a0 = v0 ? acc[nt][0] : 0.f;
        float a1 = v0 ? acc[nt][1] : 0.f;
        float a2 = v1 ? acc[nt][2] : 0.f;
        float a3 = v1 ? acc[nt][3] : 0.f;
        if (v0) Co[(size_t)r0 * 32 + (ch >> 1)] = packh2(a0, a1);
        if (v1) Co[(size_t)r1 * 32 + (ch >> 1)] = packh2(a2, a3);
        float s0 = a0 + a2;
        float s1 = a1 + a3;
        float q0 = a0 * a0 + a2 * a2;
        float q1 = a1 * a1 + a3 * a3;
#pragma unroll
        for (int d = 4; d < 32; d <<= 1) {
            s0 += __shfl_xor_sync(0xffffffffu, s0, d);
            s1 += __shfl_xor_sync(0xffffffffu, s1, d);
            q0 += __shfl_xor_sync(0xffffffffu, q0, d);
            q1 += __shfl_xor_sync(0xffffffffu, q1, d);
        }
        if (lane < 4) {
            atomicAdd(&csum[ch], s0);
            atomicAdd(&csum[ch + 1], s1);
            atomicAdd(&csq[ch], q0);
            atomicAdd(&csq[ch + 1], q1);
        }
    }
    __syncthreads();
    if (tid < 64)       atomicAdd(&statsg[tid], csum[tid]);
    else if (tid < 128) atomicAdd(&statsg[tid], csq[tid - 64]);
}

__device__ __forceinline__ void load_coef(float* sc, const float* __restrict__ stats,
                                          const float* __restrict__ g,
                                          const float* __restrict__ b, int n, int tid) {
    if (tid < 64) {
        float inv_n = 1.f / (float)n;
        float mean = stats[tid] * inv_n;
        float var = stats[64 + tid] * inv_n - mean * mean;
        float a = g[tid] * rsqrtf(var + 1e-3f);
        sc[tid] = a;
        sc[64 + tid] = b[tid] - mean * a;
    }
}

// ---------------- prepack (all 66 fp16 n-major tiles, one kernel) ----------------
__global__ void k_prepack_all(const float* __restrict__ Wlw, const float* __restrict__ Ww,
                              const float* __restrict__ Wproj, const float* __restrict__ Wfuse,
                              const float* __restrict__ Wc1, const float* __restrict__ Wc2,
                              unsigned* __restrict__ pack, unsigned* __restrict__ packc) {
    int t = blockIdx.x;     // 0..65
    const float* src;
    unsigned* ph;
    if (t < 3)       { src = Wlw  + t * 4096;        ph = pack  + (size_t)t * 2304; }
    else if (t < 6)  { src = Ww   + (t - 3) * 4096;  ph = pack  + (size_t)t * 2304; }
    else if (t < 10) { src = Wproj+ (t - 6) * 4096;  ph = pack  + (size_t)t * 2304; }
    else if (t < 12) { src = Wfuse+ (t - 10) * 4096; ph = pack  + (size_t)t * 2304; }
    else if (t < 39) { src = Wc1  + (t - 12) * 4096; ph = packc + (size_t)(t - 12) * 2304; }
    else             { src = Wc2  + (t - 39) * 4096; ph = packc + (size_t)(t - 12) * 2304; }
    for (int idx = threadIdx.x; idx < 2048; idx += 256) {
        int cout = idx & 63, p = idx >> 6;
        ph[cout * AS + p] = packh2(src[2 * p * 64 + cout], src[(2 * p + 1) * 64 + cout]);
    }
}

// Hp = fp16(relu(bn(rawF_h)) + feat)
__global__ void k_bnrelu_add_split(const unsigned* __restrict__ RawH,
                                   const float* __restrict__ stats,
                                   const float* __restrict__ g, const float* __restrict__ b,
                                   const float* __restrict__ feat,
                                   unsigned* __restrict__ Hp, int n, int total4) {
    __shared__ float sc[128];
    load_coef(sc, stats, g, b, n, threadIdx.x);
    __syncthreads();
    int i = blockIdx.x * 256 + threadIdx.x;
    if (i >= total4) return;
    int ch = (i & 15) * 4;
    float4 x = ldh4(RawH + (size_t)i * 2);
    float4 r = ((const float4*)feat)[i];
    x.x = fmaxf(x.x * sc[ch + 0] + sc[64 + ch + 0], 0.f) + r.x;
    x.y = fmaxf(x.y * sc[ch + 1] + sc[64 + ch + 1], 0.f) + r.y;
    x.z = fmaxf(x.z * sc[ch + 2] + sc[64 + ch + 2], 0.f) + r.z;
    x.w = fmaxf(x.w * sc[ch + 3] + sc[64 + ch + 3], 0.f) + r.w;
    ((uint2*)Hp)[i] = make_uint2(packh2(x.x, x.y), packh2(x.z, x.w));
}

// fp16 plane = relu(bn(P_h))
__global__ void k_bnrelu_split(const unsigned* __restrict__ Ph, const float* __restrict__ stats,
                               const float* __restrict__ g, const float* __restrict__ b,
                               unsigned* __restrict__ Hp, int n, int total4) {
    __shared__ float sc[128];
    load_coef(sc, stats, g, b, n, threadIdx.x);
    __syncthreads();
    int i = blockIdx.x * 256 + threadIdx.x;
    if (i >= total4) return;
    int ch = (i & 15) * 4;
    float4 x = ldh4(Ph + (size_t)i * 2);
    x.x = fmaxf(x.x * sc[ch + 0] + sc[64 + ch + 0], 0.f);
    x.y = fmaxf(x.y * sc[ch + 1] + sc[64 + ch + 1], 0.f);
    x.z = fmaxf(x.z * sc[ch + 2] + sc[64 + ch + 2], 0.f);
    x.w = fmaxf(x.w * sc[ch + 3] + sc[64 + ch + 3], 0.f);
    ((uint2*)Hp)[i] = make_uint2(packh2(x.x, x.y), packh2(x.z, x.w));
}

// ---------------- tensor-core kernels ----------------
// 7 GEMMs sharing A=feat (fp16-converted in staging) + fused adp softmax.
__global__ __launch_bounds__(NTHR, 4)
void k_mma_gemm7(const float* __restrict__ feat, const float* __restrict__ Wa,
                 const unsigned* __restrict__ pack, unsigned* __restrict__ bufs,
                 float* __restrict__ adp, float* __restrict__ statsg, int n) {
    extern __shared__ unsigned sm[];     // A:[0,4608) B:[4608,6912)
    __shared__ float csum[64], csq[64];
    __shared__ float wa[192];
    const int tidx[7] = {0, 1, 2, 6, 7, 8, 9};
    int tid = threadIdx.x, wid = tid >> 5, lane = tid & 31;
    int row0 = blockIdx.x * TM;
    if (tid < 192) wa[tid] = Wa[tid];
    stage_Bc(sm + COFF_B, pack + (size_t)tidx[0] * 2304, tid);
    cp_commit();
    __syncthreads();     // wa visible
#pragma unroll
    for (int i = 0; i < 8; ++i) {   // convert feat -> fp16 plane, fused adp
        int idx = tid + i * NTHR;
        int r = idx >> 4, c4 = idx & 15;
        int grow = row0 + r;
        float4 v = make_float4(0.f, 0.f, 0.f, 0.f);
        if (grow < n) v = *(const float4*)(feat + (size_t)grow * 64 + c4 * 4);
        a_storeh(sm, r, c4, v);
        int ch = c4 * 4;
        float s0 = v.x * wa[ch * 3 + 0] + v.y * wa[ch * 3 + 3] +
                   v.z * wa[ch * 3 + 6] + v.w * wa[ch * 3 + 9];
        float s1 = v.x * wa[ch * 3 + 1] + v.y * wa[ch * 3 + 4] +
                   v.z * wa[ch * 3 + 7] + v.w * wa[ch * 3 + 10];
        float s2 = v.x * wa[ch * 3 + 2] + v.y * wa[ch * 3 + 5] +
                   v.z * wa[ch * 3 + 8] + v.w * wa[ch * 3 + 11];
#pragma unroll
        for (int d = 1; d < 16; d <<= 1) {
            s0 += __shfl_xor_sync(0xffffffffu, s0, d);
            s1 += __shfl_xor_sync(0xffffffffu, s1, d);
            s2 += __shfl_xor_sync(0xffffffffu, s2, d);
        }
        if ((lane & 15) == 0 && grow < n) {
            float m = fmaxf(s0, fmaxf(s1, s2));
            float e0 = __expf(s0 - m), e1 = __expf(s1 - m), e2 = __expf(s2 - m);
            float inv = 1.f / (e0 + e1 + e2);
            adp[(size_t)grow * 3 + 0] = e0 * inv;
            adp[(size_t)grow * 3 + 1] = e1 * inv;
            adp[(size_t)grow * 3 + 2] = e2 * inv;
        }
    }
    cp_wait<0>();
    __syncthreads();
    for (int t = 0; t < 7; ++t) {
        if (tid < 64) { csum[tid] = 0.f; csq[tid] = 0.f; }
        __syncthreads();
        float acc[8][4] = {};
        mma_compute_h(sm, acc, wid, lane);
        epilogue_stats_h(acc, bufs + (size_t)t * ROWH, statsg + t * 128,
                         csum, csq, row0, n, wid, lane, tid);
        if (t + 1 < 7) {    // all B reads done (epilogue's internal sync)
            stage_Bc(sm + COFF_B, pack + (size_t)tidx[t + 1] * 2304, tid);
            cp_commit();
            cp_wait<0>();
        }
    }
}

// stage one conv tap via cp.async.bulk into buffer `buf` tracked by mbar `mba`
__device__ __forceinline__ void conv_stage(unsigned smb, int buf, int k,
                                           const uint4* __restrict__ AF,
                                           const int* __restrict__ idxs,
                                           const unsigned* __restrict__ packc,
                                           unsigned mba, int tid) {
    unsigned bbase = smb + (unsigned)buf * (CBUF * 4);
    if (tid < 128) {
        const void* src = AF + (size_t)idxs[tid * 27 + k] * 8;
        cpbulk(bbase + tid * (AS * 4), src, 128, mba);
    } else if (tid == 128) {
        mbar_expect(mba, CONV_TX);
        cpbulk(bbase + COFF_B * 4, packc + (size_t)k * 2304, 9216, mba);
    }
}

// gather conv (fp16), bulk-copy double-buffer pipeline; fp16 out + stats
__global__ __launch_bounds__(NTHR)
void k_mma_convh(const uint4* __restrict__ AF, const int* __restrict__ nbr,
                 const unsigned* __restrict__ packc,
                 unsigned* __restrict__ Co, float* __restrict__ statsg, int n) {
    extern __shared__ unsigned sm[];          // 2 x CBUF + idx cache
    int* idxs = (int*)(sm + 2 * CBUF);        // [TM*27]
    __shared__ float csum[64], csq[64];
    __shared__ unsigned long long mbar[2];
    int tid = threadIdx.x, wid = tid >> 5, lane = tid & 31;
    int row0 = blockIdx.x * TM;
    unsigned mb0 = (unsigned)__cvta_generic_to_shared(&mbar[0]);
    unsigned mb1 = (unsigned)__cvta_generic_to_shared(&mbar[1]);
    unsigned smb = (unsigned)__cvta_generic_to_shared(sm);
    if (tid < 64) { csum[tid] = 0.f; csq[tid] = 0.f; }
    if (tid == 0) { mbar_init(mb0, 1); mbar_init(mb1, 1); }
    {   // coalesced preload of neighbor indices
        size_t base = (size_t)row0 * 27;
        size_t lim = (size_t)n * 27;
        for (int i = tid; i < TM * 27; i += NTHR) {
            size_t pos = base + i;
            idxs[i] = (pos < lim) ? __ldg(&nbr[pos]) : 0;
        }
    }
    __syncthreads();
    int ph0 = 0, ph1 = 0;
    conv_stage(smb, 0, 0, AF, idxs, packc, mb0, tid);
    float acc[8][4] = {};
    for (int k = 0; k < 27; ++k) {
        if (k + 1 < 27)
            conv_stage(smb, (k + 1) & 1, k + 1, AF, idxs, packc,
                       (k & 1) ? mb0 : mb1, tid);
        if (k & 1) { mbar_wait(mb1, ph1); ph1 ^= 1; }
        else       { mbar_wait(mb0, ph0); ph0 ^= 1; }
        mma_compute_h(sm + (k & 1) * CBUF, acc, wid, lane);
        __syncthreads();
    }
    epilogue_stats_h(acc, Co, statsg, csum, csq, row0, n, wid, lane, tid);
}

// per-scale (gridDim.y=3): P = exp((relu(bn(P)) - mean[cl]) @ W_w); den += P
__global__ __launch_bounds__(NTHR)
void k_mma_submean_exp(unsigned* __restrict__ bufs, const float* __restrict__ statsb,
                       const float* __restrict__ glw, const float* __restrict__ blw,
                       const unsigned* __restrict__ pack, const float* __restrict__ mean,
                       const float* __restrict__ cnt,
                       const int* __restrict__ cl0, const int* __restrict__ cl1,
                       const int* __restrict__ cl2, float* __restrict__ den, int n) {
    extern __shared__ unsigned buf[];
    __shared__ float coef[128];
    __shared__ int   cls[TM];
    __shared__ float cinv[TM];
    int s = blockIdx.y;
    const int* cl = (s == 0) ? cl0 : ((s == 1) ? cl1 : cl2);
    int soff = c_soff[s];
    unsigned* P = bufs + (size_t)s * ROWH;
    int tid = threadIdx.x, wid = tid >> 5, lane = tid & 31;
    int row0 = blockIdx.x * TM;
    load_coef(coef, statsb + s * 128, glw + s * 64, blw + s * 64, n, tid);
    if (tid < 128) {
        int r = row0 + tid;
        int c = (r < n) ? cl[r] : 0;
        cls[tid] = c;
        cinv[tid] = 1.f / fmaxf(cnt[soff + c], 1.f);
    }
    stage_Bc(buf + COFF_B, pack + (size_t)(3 + s) * 2304, tid);
    cp_commit();
    __syncthreads();
#pragma unroll
    for (int i = 0; i < 8; ++i) {
        int idx = tid + i * NTHR;
        int r = idx >> 4, c4 = idx & 15;
        int grow = row0 + r;
        float4 vv = make_float4(0.f, 0.f, 0.f, 0.f);
        if (grow < n) {
            vv = ldh4(P + (size_t)grow * 32 + c4 * 2);
            float4 ms = *(const float4*)(mean + (size_t)(soff + cls[r]) * 64 + c4 * 4);
            float ci = cinv[r];
            int ch = c4 * 4;
            vv.x = fmaxf(vv.x * coef[ch + 0] + coef[64 + ch + 0], 0.f) - ms.x * ci;
            vv.y = fmaxf(vv.y * coef[ch + 1] + coef[64 + ch + 1], 0.f) - ms.y * ci;
            vv.z = fmaxf(vv.z * coef[ch + 2] + coef[64 + ch + 2], 0.f) - ms.z * ci;
            vv.w = fmaxf(vv.w * coef[ch + 3] + coef[64 + ch + 3], 0.f) - ms.w * ci;
        }
        a_storeh(buf, r, c4, vv);
    }
    cp_wait<0>();
    __syncthreads();
    float acc[8][4] = {};
    mma_compute_h(buf, acc, wid, lane);
    int g = lane >> 2, c = lane & 3;
    int lr0 = wid * 16 + g, lr1 = lr0 + 8;
    int r0 = row0 + lr0, r1 = row0 + lr1;
    float* d0 = den + (size_t)(soff + cls[lr0]) * 64;
    float* d1 = den + (size_t)(soff + cls[lr1]) * 64;
#pragma unroll
    for (int nt = 0; nt < 8; ++nt) {
        int ch = nt * 8 + 2 * c;
        if (r0 < n) {
            float e0 = __expf(acc[nt][0]), e1 = __expf(acc[nt][1]);
            P[(size_t)r0 * 32 + (ch >> 1)] = packh2(e0, e1);
            red_add_v2(d0 + ch, e0, e1);
        }
        if (r1 < n) {
            float e2 = __expf(acc[nt][2]), e3 = __expf(acc[nt][3]);
            P[(size_t)r1 * 32 + (ch >> 1)] = packh2(e2, e3);
            red_add_v2(d1 + ch, e2, e3);
        }
    }
}

// fuse GEMM: rawF_h = relu(bn(Q3))@Wf[0:64] + mix@Wf[64:128]; fp16 out + stats
__global__ __launch_bounds__(NTHR)
void k_mma_gemm2(const unsigned* __restrict__ Qh, const float* __restrict__ stats,
                 const float* __restrict__ gg, const float* __restrict__ bb,
                 const unsigned* __restrict__ tiles, const float* __restrict__ segS,
                 const int* __restrict__ cl0, const int* __restrict__ cl1,
                 const int* __restrict__ cl2, const float* __restrict__ adp,
                 unsigned* __restrict__ Co, float* __restrict__ statsg, int n) {
    extern __shared__ unsigned buf[];
    __shared__ float csum[64], csq[64];
    __shared__ float coef[128];
    __shared__ int   cls[3][TM];
    __shared__ float sad[3][TM];
    int tid = threadIdx.x, wid = tid >> 5, lane = tid & 31;
    int row0 = blockIdx.x * TM;
    if (tid < 64) { csum[tid] = 0.f; csq[tid] = 0.f; }
    load_coef(coef, stats, gg, bb, n, tid);
    if (tid < 128) {
        int r = row0 + tid;
        bool v = r < n;
        cls[0][tid] = v ? cl0[r] : 0;
        cls[1][tid] = v ? cl1[r] : 0;
        cls[2][tid] = v ? cl2[r] : 0;
        sad[0][tid] = v ? adp[(size_t)r * 3 + 0] : 0.f;
        sad[1][tid] = v ? adp[(size_t)r * 3 + 1] : 0.f;
        sad[2][tid] = v ? adp[(size_t)r * 3 + 2] : 0.f;
    }
    __syncthreads();
    float acc[8][4] = {};
#pragma unroll
    for (int p = 0; p < 2; ++p) {
        stage_Bc(buf + COFF_B, tiles + (size_t)p * 2304, tid);
        cp_commit();
#pragma unroll
        for (int i = 0; i < 8; ++i) {
            int idx = tid + i * NTHR;
            int r = idx >> 4, c4 = idx & 15;
            int grow = row0 + r;
            float4 vv = make_float4(0.f, 0.f, 0.f, 0.f);
            if (grow < n) {
                if (p == 0) {
                    vv = ldh4(Qh + (size_t)grow * 32 + c4 * 2);
                    int ch = c4 * 4;
                    vv.x = fmaxf(vv.x * coef[ch + 0] + coef[64 + ch + 0], 0.f);
                    vv.y = fmaxf(vv.y * coef[ch + 1] + coef[64 + ch + 1], 0.f);
                    vv.z = fmaxf(vv.z * coef[ch + 2] + coef[64 + ch + 2], 0.f);
                    vv.w = fmaxf(vv.w * coef[ch + 3] + coef[64 + ch + 3], 0.f);
                } else {
                    float w0 = sad[0][r], w1 = sad[1][r], w2 = sad[2][r];
                    float4 a = *(const float4*)(segS + (size_t)(0 + cls[0][r]) * 64 + c4 * 4);
                    float4 bv = *(const float4*)(segS + (size_t)(4096 + cls[1][r]) * 64 + c4 * 4);
                    float4 cc = *(const float4*)(segS + (size_t)(36864 + cls[2][r]) * 64 + c4 * 4);
                    vv.x = w0 * a.x + w1 * bv.x + w2 * cc.x;
                    vv.y = w0 * a.y + w1 * bv.y + w2 * cc.y;
                    vv.z = w0 * a.z + w1 * bv.z + w2 * cc.z;
                    vv.w = w0 * a.w + w1 * bv.w + w2 * cc.w;
                }
            }
            a_storeh(buf, r, c4, vv);
        }
        cp_wait<0>();
        __syncthreads();
        mma_compute_h(buf, acc, wid, lane);
        __syncthreads();
    }
    epilogue_stats_h(acc, Co, statsg, csum, csq, row0, n, wid, lane, tid);
}

// ---------------- small / elementwise kernels ----------------
// per-scale (gridDim.y=3): mean-arena += relu(bn(P_h)), cnt++
__global__ void k_segsum3(const unsigned* __restrict__ bufs, const float* __restrict__ statsb,
                          const float* __restrict__ glw, const float* __restrict__ blw,
                          const int* __restrict__ cl0, const int* __restrict__ cl1,
                          const int* __restrict__ cl2, float* __restrict__ mean,
                          float* __restrict__ cnt, int n) {
    __shared__ float sc[128];
    int s = blockIdx.y;
    load_coef(sc, statsb + s * 128, glw + s * 64, blw + s * 64, n, threadIdx.x);
    __syncthreads();
    int row = blockIdx.x * blockDim.x + threadIdx.x;
    if (row >= n) return;
    const int* cl = (s == 0) ? cl0 : ((s == 1) ? cl1 : cl2);
    int c = c_soff[s] + cl[row];
    const unsigned* p = bufs + (size_t)s * ROWH + (size_t)row * 32;
    float* sg = mean + (size_t)c * 64;
#pragma unroll
    for (int c4 = 0; c4 < 16; ++c4) {
        float4 x = ldh4(p + c4 * 2);
        x.x = fmaxf(x.x * sc[c4 * 4 + 0] + sc[64 + c4 * 4 + 0], 0.f);
        x.y = fmaxf(x.y * sc[c4 * 4 + 1] + sc[64 + c4 * 4 + 1], 0.f);
        x.z = fmaxf(x.z * sc[c4 * 4 + 2] + sc[64 + c4 * 4 + 2], 0.f);
        x.w = fmaxf(x.w * sc[c4 * 4 + 3] + sc[64 + c4 * 4 + 3], 0.f);
        red_add_v4(sg + c4 * 4, x);
    }
    atomicAdd(&cnt[c], 1.f);
}

// per-scale (gridDim.y=3): segS += relu(bn(Q_h)) * expP_h / (den[cl]+1e-6)
__global__ void k_pw3(const unsigned* __restrict__ bufs, const float* __restrict__ statsb,
                      const float* __restrict__ gproj, const float* __restrict__ bproj,
                      const float* __restrict__ den,
                      const int* __restrict__ cl0, const int* __restrict__ cl1,
                      const int* __restrict__ cl2, float* __restrict__ segS, int n) {
    __shared__ float sc[128];
    int s = blockIdx.y;
    load_coef(sc, statsb + (3 + s) * 128, gproj + s * 64, bproj + s * 64, n, threadIdx.x);
    __syncthreads();
    int row = blockIdx.x * blockDim.x + threadIdx.x;
    if (row >= n) return;
    const int* cl = (s == 0) ? cl0 : ((s == 1) ? cl1 : cl2);
    int c = c_soff[s] + cl[row];
    const unsigned* q = bufs + (size_t)(3 + s) * ROWH + (size_t)row * 32;
    const unsigned* p = bufs + (size_t)s * ROWH + (size_t)row * 32;
    const float* d = den + (size_t)c * 64;
    float* sg = segS + (size_t)c * 64;
#pragma unroll
    for (int c4 = 0; c4 < 16; ++c4) {
        float4 qv = ldh4(q + c4 * 2);
        float4 pv = ldh4(p + c4 * 2);
        float4 dv = *(const float4*)(d + c4 * 4);
        float4 o;
        o.x = fmaxf(qv.x * sc[c4 * 4 + 0] + sc[64 + c4 * 4 + 0], 0.f) * pv.x / (dv.x + 1e-6f);
        o.y = fmaxf(qv.y * sc[c4 * 4 + 1] + sc[64 + c4 * 4 + 1], 0.f) * pv.y / (dv.y + 1e-6f);
        o.z = fmaxf(qv.z * sc[c4 * 4 + 2] + sc[64 + c4 * 4 + 2], 0.f) * pv.z / (dv.z + 1e-6f);
        o.w = fmaxf(qv.w * sc[c4 * 4 + 3] + sc[64 + c4 * 4 + 3], 0.f) * pv.w / (dv.w + 1e-6f);
        red_add_v4(sg + c4 * 4, o);
    }
}

// out = relu(bn_c2(H_h) + F), F = relu(bn_fuse(rawF_h)) + feat (recomputed)
__global__ void k_final(const unsigned* __restrict__ Hh, const float* __restrict__ statsC,
                        const float* __restrict__ gC, const float* __restrict__ bC,
                        const unsigned* __restrict__ RawH, const float* __restrict__ statsF,
                        const float* __restrict__ gF, const float* __restrict__ bF,
                        const float* __restrict__ feat, float* __restrict__ out,
                        int n, int total4) {
    __shared__ float sc[128];   // conv2 coef
    __shared__ float sf[128];   // fuse coef
    load_coef(sc, statsC, gC, bC, n, threadIdx.x);
    if (threadIdx.x >= 128) load_coef(sf, statsF, gF, bF, n, threadIdx.x - 128);
    __syncthreads();
    int i = blockIdx.x * 256 + threadIdx.x;
    if (i >= total4) return;
    int ch = (i & 15) * 4;
    float4 h = ldh4(Hh + (size_t)i * 2);
    float4 w = ldh4(RawH + (size_t)i * 2);
    float4 r = ((const float4*)feat)[i];
    float f0 = fmaxf(w.x * sf[ch + 0] + sf[64 + ch + 0], 0.f) + r.x;
    float f1 = fmaxf(w.y * sf[ch + 1] + sf[64 + ch + 1], 0.f) + r.y;
    float f2 = fmaxf(w.z * sf[ch + 2] + sf[64 + ch + 2], 0.f) + r.z;
    float f3 = fmaxf(w.w * sf[ch + 3] + sf[64 + ch + 3], 0.f) + r.w;
    float4 x;
    x.x = fmaxf(h.x * sc[ch + 0] + sc[64 + ch + 0] + f0, 0.f);
    x.y = fmaxf(h.y * sc[ch + 1] + sc[64 + ch + 1] + f1, 0.f);
    x.z = fmaxf(h.z * sc[ch + 2] + sc[64 + ch + 2] + f2, 0.f);
    x.w = fmaxf(h.w * sc[ch + 3] + sc[64 + ch + 3] + f3, 0.f);
    ((float4*)out)[i] = x;
}

// ---------------------------------------------------------------------------
extern "C" void kernel_launch(void* const* d_in, const int* in_sizes, int n_in,
                              void* d_out, int out_size) {
    const float* feat   = (const float*)d_in[0];
    const int*   cl0    = (const int*)d_in[1];
    const int*   cl1    = (const int*)d_in[2];
    const int*   cl2    = (const int*)d_in[3];
    const int*   nbr    = (const int*)d_in[4];
    const float* W_lw   = (const float*)d_in[5];
    const float* g_lw   = (const float*)d_in[6];
    const float* b_lw   = (const float*)d_in[7];
    const float* W_w    = (const float*)d_in[8];
    const float* W_proj = (const float*)d_in[9];
    const float* g_proj = (const float*)d_in[10];
    const float* b_proj = (const float*)d_in[11];
    const float* W_adp  = (const float*)d_in[12];
    const float* W_fuse = (const float*)d_in[13];
    const float* g_fuse = (const float*)d_in[14];
    const float* b_fuse = (const float*)d_in[15];
    const float* W_c1   = (const float*)d_in[16];
    const float* g_c1   = (const float*)d_in[17];
    const float* b_c1   = (const float*)d_in[18];
    const float* W_c2   = (const float*)d_in[19];
    const float* g_c2   = (const float*)d_in[20];
    const float* b_c2   = (const float*)d_in[21];
    float* out = (float*)d_out;
    int n = in_sizes[1];

    float *pSegAll, *pStats, *pAdp;
    unsigned *pBufH, *pPack, *pPackC, *pFph;
    cudaGetSymbolAddress((void**)&pBufH, g_bufsH);
    cudaGetSymbolAddress((void**)&pFph, g_fph);
    cudaGetSymbolAddress((void**)&pSegAll, g_segAll);
    cudaGetSymbolAddress((void**)&pStats, g_statsA);
    cudaGetSymbolAddress((void**)&pAdp, g_adpv);
    cudaGetSymbolAddress((void**)&pPack, g_wpack);
    cudaGetSymbolAddress((void**)&pPackC, g_wpackc);
    float* pMean = pSegAll;
    float* pDen  = pSegAll + SEGSZ;
    float* pSegS = pSegAll + 2 * SEGSZ;
    float* pCnt  = pSegAll + 3 * SEGSZ;

    const int GB = (n + TM - 1) / TM;
    const int EB = (n + 255) / 256;
    const int total4 = n * 16;
    const int SB = (total4 + 255) / 256;
    const int SM_1  = CBUF * 4;                     // 27648B (fp16 A + B)
    const int SM_CV = (2 * CBUF + TM * 27) * 4;     // 69120B (idx cache kept)

    cudaFuncSetAttribute(k_mma_gemm7, cudaFuncAttributeMaxDynamicSharedMemorySize, SM_1);
    cudaFuncSetAttribute(k_mma_submean_exp, cudaFuncAttributeMaxDynamicSharedMemorySize, SM_1);
    cudaFuncSetAttribute(k_mma_gemm2, cudaFuncAttributeMaxDynamicSharedMemorySize, SM_1);
    cudaFuncSetAttribute(k_mma_convh, cudaFuncAttributeMaxDynamicSharedMemorySize, SM_CV);

    const uint4* AF = (const uint4*)pFph;
    unsigned* Qh3 = pBufH + 6 * ROWH;
    unsigned* RawFH = pBufH;                // slot 0 (P0, free after pw3)
    unsigned* C1H  = pBufH + 1 * ROWH;      // slot 1
    unsigned* C2H  = pBufH + 2 * ROWH;      // slot 2

    k_prepack_all<<<66, 256>>>(W_lw, W_w, W_proj, W_fuse, W_c1, W_c2, pPack, pPackC);
    cudaMemsetAsync(pStats, 0, 10 * 128 * sizeof(float));
    cudaMemsetAsync(pSegAll, 0, (3 * SEGSZ + SEGTOT) * sizeof(float));

    // 7 feat-GEMMs (feat converted in staging) + fused adp
    k_mma_gemm7<<<GB, NTHR, SM_1>>>(feat, W_adp, pPack, pBufH, pAdp, pStats, n);

    // cluster attention, all 3 scales batched
    k_segsum3<<<dim3(EB, 3), 256>>>(pBufH, pStats, g_lw, b_lw, cl0, cl1, cl2,
                                    pMean, pCnt, n);
    k_mma_submean_exp<<<dim3(GB, 3), NTHR, SM_1>>>(pBufH, pStats, g_lw, b_lw, pPack,
                                                   pMean, pCnt, cl0, cl1, cl2, pDen, n);
    k_pw3<<<dim3(EB, 3), 256>>>(pBufH, pStats, g_proj, b_proj, pDen,
                                cl0, cl1, cl2, pSegS, n);

    // fused: rawF_h = [relu(bn(Q3)), mix] @ W_fuse  (F recomputed in k_final)
    k_mma_gemm2<<<GB, NTHR, SM_1>>>(Qh3, pStats + 6 * 128, g_proj + 192, b_proj + 192,
                                    pPack + (size_t)10 * 2304, pSegS,
                                    cl0, cl1, cl2, pAdp, RawFH, pStats + 7 * 128, n);
    k_bnrelu_add_split<<<SB, 256>>>(RawFH, pStats + 7 * 128, g_fuse, b_fuse, feat,
                                    pFph, n, total4);
    // conv1 -> split ; conv2 -> final (recomputes F)
    k_mma_convh<<<GB, NTHR, SM_CV>>>(AF, nbr, pPackC, C1H, pStats + 8 * 128, n);
    k_bnrelu_split<<<SB, 256>>>(C1H, pStats + 8 * 128, g_c1, b_c1, pFph, n, total4);
    k_mma_convh<<<GB, NTHR, SM_CV>>>(AF, nbr, pPackC + (size_t)27 * 2304,
                                     C2H, pStats + 9 * 128, n);
    k_final<<<SB, 256>>>(C2H, pStats + 9 * 128, g_c2, b_c2,
                         RawFH, pStats + 7 * 128, g_fuse, b_fuse,
                         feat, out, n, total4);
}